// round 14
// baseline (speedup 1.0000x reference)
#include <cuda_runtime.h>
#include <math.h>
#include <stdint.h>

#define BATCH 2
#define SEQ   2048
#define EMB   1024
#define NH    16
#define HD    64
#define NTOK  (BATCH*SEQ)   // 4096

// Scratch (allocation-free).
static __device__ float g_x[(size_t)NTOK * EMB];            // tf32-rounded x
static __device__ float g_qkv[(size_t)NTOK * 3 * EMB];      // QKV projections
static __device__ float g_attn[(size_t)NTOK * EMB];         // attention output (tf32 bits)
static __device__ float g_w_inT[(size_t)3 * EMB * EMB];     // w_in^T  (tf32 bits)
static __device__ float g_w_outT[(size_t)EMB * EMB];        // w_out^T (tf32 bits)

// ===========================================================================
// PTX helpers (sm_80-baseline: mma.sync tf32, ldmatrix, cp.async)
// ===========================================================================
__device__ __forceinline__ uint32_t smem_u32(const void* p) {
    uint32_t a;
    asm("{ .reg .u64 t; cvta.to.shared.u64 t, %1; cvt.u32.u64 %0, t; }"
        : "=r"(a) : "l"(p));
    return a;
}
__device__ __forceinline__ uint32_t f2tf32(float x) {
    uint32_t u;
    asm("cvt.rna.tf32.f32 %0, %1;" : "=r"(u) : "f"(x));
    return u;
}
__device__ __forceinline__ void ldsm_x4(uint32_t* r, uint32_t addr) {
    asm volatile("ldmatrix.sync.aligned.m8n8.x4.shared.b16 {%0,%1,%2,%3}, [%4];"
                 : "=r"(r[0]), "=r"(r[1]), "=r"(r[2]), "=r"(r[3]) : "r"(addr));
}
__device__ __forceinline__ void ldsm_x2(uint32_t* r, uint32_t addr) {
    asm volatile("ldmatrix.sync.aligned.m8n8.x2.shared.b16 {%0,%1}, [%2];"
                 : "=r"(r[0]), "=r"(r[1]) : "r"(addr));
}
__device__ __forceinline__ void mma_tf32(float* c, const uint32_t* a, const uint32_t* b) {
    asm volatile(
        "mma.sync.aligned.m16n8k8.row.col.f32.tf32.tf32.f32 "
        "{%0,%1,%2,%3}, {%4,%5,%6,%7}, {%8,%9}, {%0,%1,%2,%3};"
        : "+f"(c[0]), "+f"(c[1]), "+f"(c[2]), "+f"(c[3])
        : "r"(a[0]), "r"(a[1]), "r"(a[2]), "r"(a[3]), "r"(b[0]), "r"(b[1]));
}
__device__ __forceinline__ void cp_async16(uint32_t dst, const void* src) {
    asm volatile("cp.async.cg.shared.global [%0], [%1], 16;" :: "r"(dst), "l"(src));
}
#define CP_COMMIT() asm volatile("cp.async.commit_group;" ::: "memory")
#define CP_WAIT(n)  asm volatile("cp.async.wait_group %0;" :: "n"(n) : "memory")

// ===========================================================================
// Pre-passes: tf32 rounding + transposed-rounded weights
// ===========================================================================
__global__ void round_tf32_kernel(const float* __restrict__ in, float* __restrict__ out)
{
    int i = (blockIdx.x * blockDim.x + threadIdx.x) * 4;
    float4 v = *(const float4*)(in + i);
    uint4 t = make_uint4(f2tf32(v.x), f2tf32(v.y), f2tf32(v.z), f2tf32(v.w));
    *(uint4*)(out + i) = t;
}

__global__ void transpose_round_kernel(const float* __restrict__ in, float* __restrict__ out,
                                       int R, int C)
{
    __shared__ float t[32][33];
    int c0 = blockIdx.x * 32, r0 = blockIdx.y * 32;
    int x = threadIdx.x, y = threadIdx.y;   // block (32,8)
#pragma unroll
    for (int i = 0; i < 32; i += 8)
        t[y + i][x] = in[(size_t)(r0 + y + i) * C + c0 + x];
    __syncthreads();
#pragma unroll
    for (int i = 0; i < 32; i += 8)
        out[(size_t)(c0 + y + i) * R + r0 + x] = __uint_as_float(f2tf32(t[x][y + i]));
}

// ===========================================================================
// TF32 mma GEMM + bias, cp.async 3-stage pipeline.
// C[M,N] = A[M,K] @ Bt[N,K]^T + bias[N]. A, Bt pre-rounded to tf32 bits.
// CTA 128x128x32, 256 threads, 8 warps (2x4), warp tile 64x32.
// Dynamic smem: stage s at s*32768 (A 16KB | B 16KB), 3 stages = 96KB.
// ===========================================================================
#define GEMM_SMEM_BYTES (3 * 32768)

__global__ __launch_bounds__(256, 2)
void gemm_mma(const float* __restrict__ A, const float* __restrict__ Bt,
              const float* __restrict__ bias, float* __restrict__ C,
              int M, int N, int K)
{
    extern __shared__ char gsm[];
    const uint32_t sbase = smem_u32(gsm);

    const int tid  = threadIdx.x;
    const int wid  = tid >> 5, lane = tid & 31;
    const int wm   = wid >> 2;      // 0..1
    const int wn   = wid & 3;       // 0..3
    const int mBase = blockIdx.y * 128;
    const int nBase = blockIdx.x * 128;

    const int a_tile = lane >> 3, a_r = lane & 7;
    const int b_tile = (lane >> 3) & 1, b_r = lane & 7;

    const float* Ag = A  + (size_t)mBase * K;
    const float* Bg = Bt + (size_t)nBase * K;

    const int ld_row = tid >> 3, ld_kq = tid & 7;   // 32 rows per pass, 4 passes

    auto issue = [&](int stage, int k0) {
#pragma unroll
        for (int it = 0; it < 4; it++) {
            int row = ld_row + it * 32;
            uint32_t off = row * 128 + ld_kq * 16;
            off ^= (off >> 3) & 0x70;
            cp_async16(sbase + stage * 32768 + off,
                       Ag + (size_t)row * K + k0 + ld_kq * 4);
            cp_async16(sbase + stage * 32768 + 16384 + off,
                       Bg + (size_t)row * K + k0 + ld_kq * 4);
        }
        CP_COMMIT();
    };

    float c[4][4][4];
#pragma unroll
    for (int mi = 0; mi < 4; mi++)
#pragma unroll
        for (int ni = 0; ni < 4; ni++)
#pragma unroll
            for (int j = 0; j < 4; j++) c[mi][ni][j] = 0.f;

    const int niter = K / 32;
    issue(0, 0);
    issue(1, 32);

    for (int i = 0; i < niter; i++) {
        if (i + 1 < niter) { CP_WAIT(1); } else { CP_WAIT(0); }
        __syncthreads();
        if (i + 2 < niter) {
            int s = (i + 2) % 3;
            issue(s, (i + 2) * 32);
        }

        const uint32_t as_b = sbase + (i % 3) * 32768;
        const uint32_t bs_b = as_b + 16384;

#pragma unroll
        for (int kk = 0; kk < 32; kk += 8) {
            uint32_t af[4][4], bf[4][2];
#pragma unroll
            for (int mi = 0; mi < 4; mi++) {
                int m = wm * 64 + mi * 16 + a_r + (a_tile & 1) * 8;
                int k = kk + (a_tile >> 1) * 4;
                uint32_t off = m * 128 + k * 4;
                off ^= (off >> 3) & 0x70;
                ldsm_x4(af[mi], as_b + off);
            }
#pragma unroll
            for (int ni = 0; ni < 4; ni++) {
                int n = wn * 32 + ni * 8 + b_r;
                int k = kk + b_tile * 4;
                uint32_t off = n * 128 + k * 4;
                off ^= (off >> 3) & 0x70;
                ldsm_x2(bf[ni], bs_b + off);
            }
#pragma unroll
            for (int mi = 0; mi < 4; mi++)
#pragma unroll
                for (int ni = 0; ni < 4; ni++)
                    mma_tf32(c[mi][ni], af[mi], bf[ni]);
        }
    }

    __syncthreads();
    const int r = lane >> 2, q = lane & 3;
#pragma unroll
    for (int mi = 0; mi < 4; mi++) {
        int m0 = mBase + wm * 64 + mi * 16 + r;
#pragma unroll
        for (int ni = 0; ni < 4; ni++) {
            int n0 = nBase + wn * 32 + ni * 8 + q * 2;
            float2 bv = *(const float2*)(bias + n0);
            float2 o0, o1;
            o0.x = c[mi][ni][0] + bv.x; o0.y = c[mi][ni][1] + bv.y;
            o1.x = c[mi][ni][2] + bv.x; o1.y = c[mi][ni][3] + bv.y;
            *(float2*)(C + (size_t)m0 * N + n0)       = o0;
            *(float2*)(C + (size_t)(m0 + 8) * N + n0) = o1;
        }
    }
}

// ===========================================================================
// Flash attention, TF32 mma.sync. One CTA = 128 queries x (batch, head).
// 256 threads, 8 warps; warp w owns query rows w*16..w*16+15 (1 m16 tile).
// KV tiles of 64, loaded gmem->smem directly at loop top (no register
// prefetch: launch_bounds(256,2) caps regs at 128; the R13 reg-buffer
// spilled to local and regressed). 16 warps/SM hide the LDG latency.
// smem rows stride AST=68 (272B): ldmatrix row step == 1 mod 8 banks-of-16B
// -> conflict-free.  smem: Qs 128x68 | Ks 64x68 | Vt 64x68 | Ps 128x68.
//
// B-fragment gather via one ldsm_x4 over a 16(n) x 8(k) region:
//   tmp[0]=n[0:8),k[0:4)  tmp[1]=n[0:8),k[4:8)  tmp[2]=n[8:16),k[0:4)  tmp[3]=n[8:16),k[4:8)
// -> bf[2np]={tmp0,tmp1}, bf[2np+1]={tmp2,tmp3}
// ===========================================================================
#define AST 68
#define ATTN_SMEM_BYTES ((128*AST + 64*AST + 64*AST + 128*AST) * 4)

__global__ __launch_bounds__(256, 2)
void mha_mma_kernel(const float* __restrict__ qkv, float* __restrict__ out)
{
    extern __shared__ float smf[];
    float* Qs = smf;                 // [m][d]
    float* Ks = Qs + 128 * AST;      // [kv][d]
    float* Vt = Ks + 64 * AST;       // [d][kv]
    float* Ps = Vt + 64 * AST;       // [m][kv]
    const uint32_t qs_b = smem_u32(Qs), ks_b = smem_u32(Ks);
    const uint32_t vt_b = smem_u32(Vt), ps_b = smem_u32(Ps);

    const int tid  = threadIdx.x;
    const int warp = tid >> 5, lane = tid & 31;
    const int r = lane >> 2, q = lane & 3;
    const int a_tile = lane >> 3, a_r = lane & 7;

    const int h  = blockIdx.y & (NH - 1);
    const int b  = blockIdx.y >> 4;
    const int q0 = blockIdx.x * 128;
    const size_t rs = 3 * EMB;

    const float* Qg = qkv + ((size_t)b * SEQ + q0) * rs + h * HD;
    const float* Kg = qkv + (size_t)b * SEQ * rs + EMB + h * HD;

    // Load Q tile (128 x 64), scale by 1/8, round to tf32.
#pragma unroll
    for (int it = 0; it < 8; it++) {
        int f = tid + it * 256;
        int m = f >> 4, c4 = f & 15;
        float4 v = *(const float4*)(Qg + (size_t)m * rs + c4 * 4);
        uint4 t = make_uint4(f2tf32(v.x * 0.125f), f2tf32(v.y * 0.125f),
                             f2tf32(v.z * 0.125f), f2tf32(v.w * 0.125f));
        *(uint4*)(Qs + m * AST + c4 * 4) = t;
    }

    float o[8][4];
#pragma unroll
    for (int ni = 0; ni < 8; ni++)
#pragma unroll
        for (int j = 0; j < 4; j++) o[ni][j] = 0.f;
    float m_st[2] = {-1e30f, -1e30f};
    float l_st[2] = {0.f, 0.f};

    __syncthreads();

    for (int kt = 0; kt < SEQ; kt += 64) {
        // K tile [kv][d] (rounded uint4) + V tile transposed [d][kv].
        // 64 rows x 16 float4-groups = 1024 items over 256 threads = 4 iters.
#pragma unroll
        for (int it = 0; it < 4; it++) {
            int f  = tid + it * 256;
            int kv = f >> 4, c4 = f & 15;
            const float* kp = Kg + (size_t)(kt + kv) * rs + c4 * 4;
            float4 kvv = *(const float4*)kp;
            float4 vvv = *(const float4*)(kp + EMB);   // V is +EMB past K
            uint4 tk = make_uint4(f2tf32(kvv.x), f2tf32(kvv.y),
                                  f2tf32(kvv.z), f2tf32(kvv.w));
            *(uint4*)(Ks + kv * AST + c4 * 4) = tk;
            Vt[(c4 * 4 + 0) * AST + kv] = __uint_as_float(f2tf32(vvv.x));
            Vt[(c4 * 4 + 1) * AST + kv] = __uint_as_float(f2tf32(vvv.y));
            Vt[(c4 * 4 + 2) * AST + kv] = __uint_as_float(f2tf32(vvv.z));
            Vt[(c4 * 4 + 3) * AST + kv] = __uint_as_float(f2tf32(vvv.w));
        }
        __syncthreads();

        // ---- S = Q @ K^T  (warp: 16 x 64) ----
        float s[8][4];
#pragma unroll
        for (int ni = 0; ni < 8; ni++)
#pragma unroll
            for (int j = 0; j < 4; j++) s[ni][j] = 0.f;

#pragma unroll
        for (int kk = 0; kk < 64; kk += 8) {
            uint32_t af[4], bf[8][2];
            {
                int m = warp * 16 + (a_tile & 1) * 8 + a_r;
                int k = kk + (a_tile >> 1) * 4;
                ldsm_x4(af, qs_b + (m * AST + k) * 4);
            }
#pragma unroll
            for (int np = 0; np < 4; np++) {
                int n = np * 16 + (a_tile >> 1) * 8 + a_r;
                int k = kk + (a_tile & 1) * 4;
                uint32_t tmp[4];
                ldsm_x4(tmp, ks_b + (n * AST + k) * 4);
                bf[np * 2][0]     = tmp[0]; bf[np * 2][1]     = tmp[1];
                bf[np * 2 + 1][0] = tmp[2]; bf[np * 2 + 1][1] = tmp[3];
            }
#pragma unroll
            for (int ni = 0; ni < 8; ni++)
                mma_tf32(s[ni], af, bf[ni]);
        }

        // ---- online softmax (rows live in 4-lane groups) ----
#pragma unroll
        for (int hh = 0; hh < 2; hh++) {
            float tmax = -1e30f;
#pragma unroll
            for (int ni = 0; ni < 8; ni++) {
                tmax = fmaxf(tmax, s[ni][hh * 2]);
                tmax = fmaxf(tmax, s[ni][hh * 2 + 1]);
            }
            tmax = fmaxf(tmax, __shfl_xor_sync(0xffffffffu, tmax, 1));
            tmax = fmaxf(tmax, __shfl_xor_sync(0xffffffffu, tmax, 2));
            float mold = m_st[hh];
            float mnew = fmaxf(mold, tmax);
            float alpha = __expf(mold - mnew);
            float sum = 0.f;
#pragma unroll
            for (int ni = 0; ni < 8; ni++) {
                float p0 = __expf(s[ni][hh * 2]     - mnew);
                float p1 = __expf(s[ni][hh * 2 + 1] - mnew);
                s[ni][hh * 2] = p0; s[ni][hh * 2 + 1] = p1;
                sum += p0 + p1;
            }
            sum += __shfl_xor_sync(0xffffffffu, sum, 1);
            sum += __shfl_xor_sync(0xffffffffu, sum, 2);
            l_st[hh] = l_st[hh] * alpha + sum;
            m_st[hh] = mnew;
#pragma unroll
            for (int ni = 0; ni < 8; ni++) {
                o[ni][hh * 2]     *= alpha;
                o[ni][hh * 2 + 1] *= alpha;
            }
        }

        // ---- store P (tf32 bits) ----
        {
            int m0 = warp * 16 + r;
#pragma unroll
            for (int ni = 0; ni < 8; ni++) {
                int col = ni * 8 + q * 2;
                uint2 p0 = make_uint2(f2tf32(s[ni][0]), f2tf32(s[ni][1]));
                uint2 p1 = make_uint2(f2tf32(s[ni][2]), f2tf32(s[ni][3]));
                *(uint2*)(Ps + m0 * AST + col)       = p0;
                *(uint2*)(Ps + (m0 + 8) * AST + col) = p1;
            }
        }
        __syncthreads();

        // ---- O += P @ V  (A from Ps, B from Vt) ----
#pragma unroll
        for (int kk = 0; kk < 64; kk += 8) {
            uint32_t af[4], bf[8][2];
            {
                int m = warp * 16 + (a_tile & 1) * 8 + a_r;
                int k = kk + (a_tile >> 1) * 4;
                ldsm_x4(af, ps_b + (m * AST + k) * 4);
            }
#pragma unroll
            for (int np = 0; np < 4; np++) {
                int n = np * 16 + (a_tile >> 1) * 8 + a_r;
                int k = kk + (a_tile & 1) * 4;
                uint32_t tmp[4];
                ldsm_x4(tmp, vt_b + (n * AST + k) * 4);
                bf[np * 2][0]     = tmp[0]; bf[np * 2][1]     = tmp[1];
                bf[np * 2 + 1][0] = tmp[2]; bf[np * 2 + 1][1] = tmp[3];
            }
#pragma unroll
            for (int ni = 0; ni < 8; ni++)
                mma_tf32(o[ni], af, bf[ni]);
        }
        __syncthreads();
    }

    // Epilogue: O / l, round to tf32 bits (feeds GEMM2), write out.
    const size_t orow = (size_t)b * SEQ + q0;
    {
        float inv0 = 1.0f / l_st[0];
        float inv1 = 1.0f / l_st[1];
        int m0 = warp * 16 + r;
#pragma unroll
        for (int ni = 0; ni < 8; ni++) {
            int col = h * HD + ni * 8 + q * 2;
            uint2 v0 = make_uint2(f2tf32(o[ni][0] * inv0), f2tf32(o[ni][1] * inv0));
            uint2 v1 = make_uint2(f2tf32(o[ni][2] * inv1), f2tf32(o[ni][3] * inv1));
            *(uint2*)(out + (orow + m0) * EMB + col)     = v0;
            *(uint2*)(out + (orow + m0 + 8) * EMB + col) = v1;
        }
    }
}

// ===========================================================================
extern "C" void kernel_launch(void* const* d_in, const int* in_sizes, int n_in,
                              void* d_out, int out_size)
{
    const float* x     = (const float*)d_in[0];
    const float* w_in  = (const float*)d_in[1];
    const float* b_in  = (const float*)d_in[2];
    const float* w_out = (const float*)d_in[3];
    const float* b_out = (const float*)d_in[4];
    float* out = (float*)d_out;

    static float* x_buf    = nullptr;
    static float* qkv_buf  = nullptr;
    static float* attn_buf = nullptr;
    static float* w_inT    = nullptr;
    static float* w_outT   = nullptr;
    static bool   init     = false;
    if (!init) {
        cudaGetSymbolAddress((void**)&x_buf,    g_x);
        cudaGetSymbolAddress((void**)&qkv_buf,  g_qkv);
        cudaGetSymbolAddress((void**)&attn_buf, g_attn);
        cudaGetSymbolAddress((void**)&w_inT,    g_w_inT);
        cudaGetSymbolAddress((void**)&w_outT,   g_w_outT);
        cudaFuncSetAttribute(mha_mma_kernel,
                             cudaFuncAttributeMaxDynamicSharedMemorySize,
                             ATTN_SMEM_BYTES);
        cudaFuncSetAttribute(gemm_mma,
                             cudaFuncAttributeMaxDynamicSharedMemorySize,
                             GEMM_SMEM_BYTES);
        init = true;
    }

    // 0) Pre-round x; transpose+round weights to K-major tf32 bits.
    round_tf32_kernel<<<NTOK * EMB / 1024, 256>>>(x, x_buf);
    transpose_round_kernel<<<dim3(3 * EMB / 32, EMB / 32), dim3(32, 8)>>>(w_in,  w_inT,  EMB, 3 * EMB);
    transpose_round_kernel<<<dim3(EMB / 32,     EMB / 32), dim3(32, 8)>>>(w_out, w_outT, EMB, EMB);

    // 1) QKV projection: [4096,1024] @ [1024,3072] + b_in   (tf32 mma, 3-stage)
    gemm_mma<<<dim3(3 * EMB / 128, NTOK / 128), 256, GEMM_SMEM_BYTES>>>(
        x_buf, w_inT, b_in, qkv_buf, NTOK, 3 * EMB, EMB);

    // 2) Attention per (batch, head), 128-query tiles (tf32 mma flash, 8 warps)
    mha_mma_kernel<<<dim3(SEQ / 128, BATCH * NH), 256, ATTN_SMEM_BYTES>>>(
        qkv_buf, attn_buf);

    // 3) Output projection: [4096,1024] @ [1024,1024] + b_out  (tf32 mma, 3-stage)
    gemm_mma<<<dim3(EMB / 128, NTOK / 128), 256, GEMM_SMEM_BYTES>>>(
        attn_buf, w_outT, b_out, out, NTOK, EMB, EMB);
}

// round 17
// speedup vs baseline: 1.2971x; 1.2971x over previous
#include <cuda_runtime.h>
#include <math.h>
#include <stdint.h>

#define BATCH 2
#define SEQ   2048
#define EMB   1024
#define NH    16
#define HD    64
#define NTOK  (BATCH*SEQ)   // 4096

// Scratch (allocation-free).
static __device__ float g_x[(size_t)NTOK * EMB];            // tf32-rounded x
static __device__ float g_qkv[(size_t)NTOK * 3 * EMB];      // QKV (tf32 bits)
static __device__ float g_vT[(size_t)BATCH * NH * HD * SEQ];// V transposed (tf32 bits)
static __device__ float g_attn[(size_t)NTOK * EMB];         // attention out (tf32 bits)
static __device__ float g_w_inT[(size_t)3 * EMB * EMB];     // w_in^T  (tf32 bits)
static __device__ float g_w_outT[(size_t)EMB * EMB];        // w_out^T (tf32 bits)

// ===========================================================================
// PTX helpers (sm_80-baseline: mma.sync tf32, ldmatrix, cp.async)
// ===========================================================================
__device__ __forceinline__ uint32_t smem_u32(const void* p) {
    uint32_t a;
    asm("{ .reg .u64 t; cvta.to.shared.u64 t, %1; cvt.u32.u64 %0, t; }"
        : "=r"(a) : "l"(p));
    return a;
}
__device__ __forceinline__ uint32_t f2tf32(float x) {
    uint32_t u;
    asm("cvt.rna.tf32.f32 %0, %1;" : "=r"(u) : "f"(x));
    return u;
}
__device__ __forceinline__ float ex2(float x) {
    float y;
    asm("ex2.approx.f32 %0, %1;" : "=f"(y) : "f"(x));
    return y;
}
__device__ __forceinline__ void ldsm_x4(uint32_t* r, uint32_t addr) {
    asm volatile("ldmatrix.sync.aligned.m8n8.x4.shared.b16 {%0,%1,%2,%3}, [%4];"
                 : "=r"(r[0]), "=r"(r[1]), "=r"(r[2]), "=r"(r[3]) : "r"(addr));
}
__device__ __forceinline__ void mma_tf32(float* c, const uint32_t* a, const uint32_t* b) {
    asm volatile(
        "mma.sync.aligned.m16n8k8.row.col.f32.tf32.tf32.f32 "
        "{%0,%1,%2,%3}, {%4,%5,%6,%7}, {%8,%9}, {%0,%1,%2,%3};"
        : "+f"(c[0]), "+f"(c[1]), "+f"(c[2]), "+f"(c[3])
        : "r"(a[0]), "r"(a[1]), "r"(a[2]), "r"(a[3]), "r"(b[0]), "r"(b[1]));
}
__device__ __forceinline__ void cp_async16(uint32_t dst, const void* src) {
    asm volatile("cp.async.cg.shared.global [%0], [%1], 16;" :: "r"(dst), "l"(src));
}
#define CP_COMMIT() asm volatile("cp.async.commit_group;" ::: "memory")
#define CP_WAIT(n)  asm volatile("cp.async.wait_group %0;" :: "n"(n) : "memory")

// ===========================================================================
// Pre-passes
// ===========================================================================
__global__ void round_tf32_kernel(const float* __restrict__ in, float* __restrict__ out)
{
    int i = (blockIdx.x * blockDim.x + threadIdx.x) * 4;
    float4 v = *(const float4*)(in + i);
    uint4 t = make_uint4(f2tf32(v.x), f2tf32(v.y), f2tf32(v.z), f2tf32(v.w));
    *(uint4*)(out + i) = t;
}

__global__ void transpose_round_kernel(const float* __restrict__ in, float* __restrict__ out,
                                       int R, int C)
{
    __shared__ float t[32][33];
    int c0 = blockIdx.x * 32, r0 = blockIdx.y * 32;
    int x = threadIdx.x, y = threadIdx.y;   // block (32,8)
#pragma unroll
    for (int i = 0; i < 32; i += 8)
        t[y + i][x] = in[(size_t)(r0 + y + i) * C + c0 + x];
    __syncthreads();
#pragma unroll
    for (int i = 0; i < 32; i += 8)
        out[(size_t)(c0 + y + i) * R + r0 + x] = __uint_as_float(f2tf32(t[x][y + i]));
}

// Transpose the V third of qkv into vT[(b*NH+h)*HD + d][tok]. qkv pre-rounded.
__global__ void transpose_v_kernel(const float* __restrict__ qkv, float* __restrict__ vT)
{
    __shared__ float t[32][33];
    int b    = blockIdx.y >> 5;        // 32 y-blocks per batch (16 h * 2 dblk)
    int rem  = blockIdx.y & 31;
    int h    = rem >> 1, dblk = rem & 1;
    int tok0 = blockIdx.x * 32, d0 = dblk * 32;
    int x = threadIdx.x, y = threadIdx.y;   // (32,8)
    const float* src = qkv + ((size_t)(b * SEQ + tok0)) * (3 * EMB) + 2 * EMB + h * HD + d0;
#pragma unroll
    for (int i = 0; i < 32; i += 8)
        t[y + i][x] = src[(size_t)(y + i) * (3 * EMB) + x];
    __syncthreads();
    float* dst = vT + ((size_t)((b * NH + h) * HD + d0)) * SEQ + tok0;
#pragma unroll
    for (int i = 0; i < 32; i += 8)
        dst[(size_t)(y + i) * SEQ + x] = t[x][y + i];
}

// ===========================================================================
// TF32 mma GEMM + bias, cp.async 3-stage pipeline.
// C[M,N] = A[M,K] @ Bt[N,K]^T + bias[N]; roundOut!=0 -> store tf32 bits.
// CTA 128x128x32, 256 threads, 8 warps (2x4), warp tile 64x32.
// ===========================================================================
#define GEMM_SMEM_BYTES (3 * 32768)

__global__ __launch_bounds__(256, 2)
void gemm_mma(const float* __restrict__ A, const float* __restrict__ Bt,
              const float* __restrict__ bias, float* __restrict__ C,
              int M, int N, int K, int roundOut)
{
    extern __shared__ char gsm[];
    const uint32_t sbase = smem_u32(gsm);

    const int tid  = threadIdx.x;
    const int wid  = tid >> 5, lane = tid & 31;
    const int wm   = wid >> 2;      // 0..1
    const int wn   = wid & 3;       // 0..3
    const int mBase = blockIdx.y * 128;
    const int nBase = blockIdx.x * 128;

    const int a_tile = lane >> 3, a_r = lane & 7;

    const float* Ag = A  + (size_t)mBase * K;
    const float* Bg = Bt + (size_t)nBase * K;

    const int ld_row = tid >> 3, ld_kq = tid & 7;

    auto issue = [&](int stage, int k0) {
#pragma unroll
        for (int it = 0; it < 4; it++) {
            int row = ld_row + it * 32;
            uint32_t off = row * 128 + ld_kq * 16;
            off ^= (off >> 3) & 0x70;
            cp_async16(sbase + stage * 32768 + off,
                       Ag + (size_t)row * K + k0 + ld_kq * 4);
            cp_async16(sbase + stage * 32768 + 16384 + off,
                       Bg + (size_t)row * K + k0 + ld_kq * 4);
        }
        CP_COMMIT();
    };

    float c[4][4][4];
#pragma unroll
    for (int mi = 0; mi < 4; mi++)
#pragma unroll
        for (int ni = 0; ni < 4; ni++)
#pragma unroll
            for (int j = 0; j < 4; j++) c[mi][ni][j] = 0.f;

    const int niter = K / 32;
    issue(0, 0);
    issue(1, 32);

    for (int i = 0; i < niter; i++) {
        if (i + 1 < niter) { CP_WAIT(1); } else { CP_WAIT(0); }
        __syncthreads();
        if (i + 2 < niter) issue((i + 2) % 3, (i + 2) * 32);

        const uint32_t as_b = sbase + (i % 3) * 32768;
        const uint32_t bs_b = as_b + 16384;

#pragma unroll
        for (int kk = 0; kk < 32; kk += 8) {
            uint32_t af[4][4], bf[4][2];
#pragma unroll
            for (int mi = 0; mi < 4; mi++) {
                int m = wm * 64 + mi * 16 + a_r + (a_tile & 1) * 8;
                int k = kk + (a_tile >> 1) * 4;
                uint32_t off = m * 128 + k * 4;
                off ^= (off >> 3) & 0x70;
                ldsm_x4(af[mi], as_b + off);
            }
            // B: 2x ldsm_x4, each covering 16(n) x 8(k).
#pragma unroll
            for (int np = 0; np < 2; np++) {
                int n = wn * 32 + np * 16 + (a_tile >> 1) * 8 + a_r;
                int k = kk + (a_tile & 1) * 4;
                uint32_t off = n * 128 + k * 4;
                off ^= (off >> 3) & 0x70;
                uint32_t tmp[4];
                ldsm_x4(tmp, bs_b + off);
                bf[np * 2][0]     = tmp[0]; bf[np * 2][1]     = tmp[1];
                bf[np * 2 + 1][0] = tmp[2]; bf[np * 2 + 1][1] = tmp[3];
            }
#pragma unroll
            for (int mi = 0; mi < 4; mi++)
#pragma unroll
                for (int ni = 0; ni < 4; ni++)
                    mma_tf32(c[mi][ni], af[mi], bf[ni]);
        }
    }

    __syncthreads();
    const int r = lane >> 2, q = lane & 3;
#pragma unroll
    for (int mi = 0; mi < 4; mi++) {
        int m0 = mBase + wm * 64 + mi * 16 + r;
#pragma unroll
        for (int ni = 0; ni < 4; ni++) {
            int n0 = nBase + wn * 32 + ni * 8 + q * 2;
            float2 bv = *(const float2*)(bias + n0);
            float v00 = c[mi][ni][0] + bv.x, v01 = c[mi][ni][1] + bv.y;
            float v10 = c[mi][ni][2] + bv.x, v11 = c[mi][ni][3] + bv.y;
            if (roundOut) {
                uint2 o0 = make_uint2(f2tf32(v00), f2tf32(v01));
                uint2 o1 = make_uint2(f2tf32(v10), f2tf32(v11));
                *(uint2*)(C + (size_t)m0 * N + n0)       = o0;
                *(uint2*)(C + (size_t)(m0 + 8) * N + n0) = o1;
            } else {
                *(float2*)(C + (size_t)m0 * N + n0)       = make_float2(v00, v01);
                *(float2*)(C + (size_t)(m0 + 8) * N + n0) = make_float2(v10, v11);
            }
        }
    }
}

// ===========================================================================
// Flash attention, TF32 mma.sync. One CTA = 128 queries x (batch, head).
// 128 threads, 4 warps; warp w owns rows w*32..w*32+31 (2 m16 tiles).
// KV tiles of 64 filled by cp.async (qkv/vT pre-rounded; no cvt in loop):
//   K(t+1) issued after post-Ps sync (hidden by PV), V(t+1) after PV sync
//   (hidden by next S+softmax). wait_group 1 before S / before PV.
// 1/sqrt(D) folded into the exp2 constant CEXP = 0.125*log2(e).
// smem rows stride AST=68: conflict-free ldmatrix.
// ===========================================================================
#define AST 68
#define ATTN_SMEM_BYTES ((128*AST + 64*AST + 64*AST + 128*AST) * 4)
#define CEXP 0.18033688f   // 0.125 * log2(e)

__global__ __launch_bounds__(128, 2)
void mha_mma_kernel(const float* __restrict__ qkv, const float* __restrict__ vT,
                    float* __restrict__ out)
{
    extern __shared__ float smf[];
    float* Qs = smf;                 // [m][d]
    float* Ks = Qs + 128 * AST;      // [kv][d]
    float* Vt = Ks + 64 * AST;       // [d][kv]
    float* Ps = Vt + 64 * AST;       // [m][kv]
    const uint32_t qs_b = smem_u32(Qs), ks_b = smem_u32(Ks);
    const uint32_t vt_b = smem_u32(Vt), ps_b = smem_u32(Ps);

    const int tid  = threadIdx.x;
    const int warp = tid >> 5, lane = tid & 31;
    const int r = lane >> 2, q = lane & 3;
    const int a_tile = lane >> 3, a_r = lane & 7;

    const int h  = blockIdx.y & (NH - 1);
    const int b  = blockIdx.y >> 4;
    const int q0 = blockIdx.x * 128;
    const size_t rs = 3 * EMB;

    const float* Qg  = qkv + ((size_t)b * SEQ + q0) * rs + h * HD;
    const float* Kg  = qkv + (size_t)b * SEQ * rs + EMB + h * HD;
    const float* Vtg = vT + ((size_t)((b * NH + h) * HD)) * SEQ;

    // cp.async lane mapping: 64 rows x 16 chunks of 16B; 8 per thread.
    const int cp_r0 = tid >> 4;     // 0..7
    const int cp_c  = tid & 15;     // 0..15

    auto issueK = [&](int kt) {
#pragma unroll
        for (int j = 0; j < 8; j++) {
            int kv = cp_r0 + j * 8;
            cp_async16(ks_b + kv * (AST * 4) + cp_c * 16,
                       Kg + (size_t)(kt + kv) * rs + cp_c * 4);
        }
        CP_COMMIT();
    };
    auto issueV = [&](int kt) {
#pragma unroll
        for (int j = 0; j < 8; j++) {
            int d = cp_r0 + j * 8;
            cp_async16(vt_b + d * (AST * 4) + cp_c * 16,
                       Vtg + (size_t)d * SEQ + kt + cp_c * 4);
        }
        CP_COMMIT();
    };

    // Q tile 128x64: raw copy (pre-rounded tf32 bits; scale folded into CEXP).
#pragma unroll
    for (int it = 0; it < 16; it++) {
        int f = tid + it * 128;
        int m = f >> 4, c4 = f & 15;
        *(uint4*)(Qs + m * AST + c4 * 4) = *(const uint4*)(Qg + (size_t)m * rs + c4 * 4);
    }

    issueK(0);
    issueV(0);

    float o[2][8][4];
#pragma unroll
    for (int mi = 0; mi < 2; mi++)
#pragma unroll
        for (int ni = 0; ni < 8; ni++)
#pragma unroll
            for (int j = 0; j < 4; j++) o[mi][ni][j] = 0.f;
    float m_st[2][2] = {{-1e30f, -1e30f}, {-1e30f, -1e30f}};
    float l_st[2][2] = {{0.f, 0.f}, {0.f, 0.f}};

    const int NT = SEQ / 64;
    for (int ti = 0; ti < NT; ti++) {
        CP_WAIT(1);            // K(ti) ready (V(ti) may be in flight)
        __syncthreads();

        // ---- S = Q @ K^T  (warp: 32 x 64) ----
        float s[2][8][4];
#pragma unroll
        for (int mi = 0; mi < 2; mi++)
#pragma unroll
            for (int ni = 0; ni < 8; ni++)
#pragma unroll
                for (int j = 0; j < 4; j++) s[mi][ni][j] = 0.f;

#pragma unroll
        for (int kk = 0; kk < 64; kk += 8) {
            uint32_t af[2][4], bf[8][2];
#pragma unroll
            for (int mi = 0; mi < 2; mi++) {
                int m = warp * 32 + mi * 16 + (a_tile & 1) * 8 + a_r;
                int k = kk + (a_tile >> 1) * 4;
                ldsm_x4(af[mi], qs_b + (m * AST + k) * 4);
            }
#pragma unroll
            for (int np = 0; np < 4; np++) {
                int n = np * 16 + (a_tile >> 1) * 8 + a_r;
                int k = kk + (a_tile & 1) * 4;
                uint32_t tmp[4];
                ldsm_x4(tmp, ks_b + (n * AST + k) * 4);
                bf[np * 2][0]     = tmp[0]; bf[np * 2][1]     = tmp[1];
                bf[np * 2 + 1][0] = tmp[2]; bf[np * 2 + 1][1] = tmp[3];
            }
#pragma unroll
            for (int mi = 0; mi < 2; mi++)
#pragma unroll
                for (int ni = 0; ni < 8; ni++)
                    mma_tf32(s[mi][ni], af[mi], bf[ni]);
        }

        // ---- online softmax on raw s (scale folded: p = 2^(CEXP*(s-m))) ----
#pragma unroll
        for (int mi = 0; mi < 2; mi++)
#pragma unroll
            for (int hh = 0; hh < 2; hh++) {
                float tmax = -1e30f;
#pragma unroll
                for (int ni = 0; ni < 8; ni++) {
                    tmax = fmaxf(tmax, s[mi][ni][hh * 2]);
                    tmax = fmaxf(tmax, s[mi][ni][hh * 2 + 1]);
                }
                tmax = fmaxf(tmax, __shfl_xor_sync(0xffffffffu, tmax, 1));
                tmax = fmaxf(tmax, __shfl_xor_sync(0xffffffffu, tmax, 2));
                float mold = m_st[mi][hh];
                float mnew = fmaxf(mold, tmax);
                float alpha = ex2((mold - mnew) * CEXP);
                float sum = 0.f;
#pragma unroll
                for (int ni = 0; ni < 8; ni++) {
                    float p0 = ex2((s[mi][ni][hh * 2]     - mnew) * CEXP);
                    float p1 = ex2((s[mi][ni][hh * 2 + 1] - mnew) * CEXP);
                    s[mi][ni][hh * 2] = p0; s[mi][ni][hh * 2 + 1] = p1;
                    sum += p0 + p1;
                }
                sum += __shfl_xor_sync(0xffffffffu, sum, 1);
                sum += __shfl_xor_sync(0xffffffffu, sum, 2);
                l_st[mi][hh] = l_st[mi][hh] * alpha + sum;
                m_st[mi][hh] = mnew;
#pragma unroll
                for (int ni = 0; ni < 8; ni++) {
                    o[mi][ni][hh * 2]     *= alpha;
                    o[mi][ni][hh * 2 + 1] *= alpha;
                }
            }

        // ---- store P (tf32 bits) ----
#pragma unroll
        for (int mi = 0; mi < 2; mi++) {
            int m0 = warp * 32 + mi * 16 + r;
#pragma unroll
            for (int ni = 0; ni < 8; ni++) {
                int col = ni * 8 + q * 2;
                uint2 p0 = make_uint2(f2tf32(s[mi][ni][0]), f2tf32(s[mi][ni][1]));
                uint2 p1 = make_uint2(f2tf32(s[mi][ni][2]), f2tf32(s[mi][ni][3]));
                *(uint2*)(Ps + m0 * AST + col)       = p0;
                *(uint2*)(Ps + (m0 + 8) * AST + col) = p1;
            }
        }
        __syncthreads();        // Ps visible; all warps done reading Ks

        if (ti + 1 < NT) issueK((ti + 1) * 64);   // hidden behind PV

        if (ti + 1 < NT) { CP_WAIT(1); } else { CP_WAIT(0); }  // V(ti) ready
        __syncthreads();

        // ---- O += P @ V ----
#pragma unroll
        for (int kk = 0; kk < 64; kk += 8) {
            uint32_t af[2][4], bf[8][2];
#pragma unroll
            for (int mi = 0; mi < 2; mi++) {
                int m = warp * 32 + mi * 16 + (a_tile & 1) * 8 + a_r;
                int k = kk + (a_tile >> 1) * 4;
                ldsm_x4(af[mi], ps_b + (m * AST + k) * 4);
            }
#pragma unroll
            for (int np = 0; np < 4; np++) {
                int n = np * 16 + (a_tile >> 1) * 8 + a_r;
                int k = kk + (a_tile & 1) * 4;
                uint32_t tmp[4];
                ldsm_x4(tmp, vt_b + (n * AST + k) * 4);
                bf[np * 2][0]     = tmp[0]; bf[np * 2][1]     = tmp[1];
                bf[np * 2 + 1][0] = tmp[2]; bf[np * 2 + 1][1] = tmp[3];
            }
#pragma unroll
            for (int mi = 0; mi < 2; mi++)
#pragma unroll
                for (int ni = 0; ni < 8; ni++)
                    mma_tf32(o[mi][ni], af[mi], bf[ni]);
        }
        __syncthreads();        // all warps done reading Vt

        if (ti + 1 < NT) issueV((ti + 1) * 64);   // hidden behind next S+softmax
    }

    // Epilogue: O / l, round to tf32 bits (feeds gemm2's raw cp.async).
    const size_t orow = (size_t)b * SEQ + q0;
#pragma unroll
    for (int mi = 0; mi < 2; mi++) {
        float inv0 = 1.0f / l_st[mi][0];
        float inv1 = 1.0f / l_st[mi][1];
        int m0 = warp * 32 + mi * 16 + r;
#pragma unroll
        for (int ni = 0; ni < 8; ni++) {
            int col = h * HD + ni * 8 + q * 2;
            uint2 v0 = make_uint2(f2tf32(o[mi][ni][0] * inv0), f2tf32(o[mi][ni][1] * inv0));
            uint2 v1 = make_uint2(f2tf32(o[mi][ni][2] * inv1), f2tf32(o[mi][ni][3] * inv1));
            *(uint2*)(out + (orow + m0) * EMB + col)     = v0;
            *(uint2*)(out + (orow + m0 + 8) * EMB + col) = v1;
        }
    }
}

// ===========================================================================
extern "C" void kernel_launch(void* const* d_in, const int* in_sizes, int n_in,
                              void* d_out, int out_size)
{
    const float* x     = (const float*)d_in[0];
    const float* w_in  = (const float*)d_in[1];
    const float* b_in  = (const float*)d_in[2];
    const float* w_out = (const float*)d_in[3];
    const float* b_out = (const float*)d_in[4];
    float* out = (float*)d_out;

    static float* x_buf    = nullptr;
    static float* qkv_buf  = nullptr;
    static float* vT_buf   = nullptr;
    static float* attn_buf = nullptr;
    static float* w_inT    = nullptr;
    static float* w_outT   = nullptr;
    static bool   init     = false;
    if (!init) {
        cudaGetSymbolAddress((void**)&x_buf,    g_x);
        cudaGetSymbolAddress((void**)&qkv_buf,  g_qkv);
        cudaGetSymbolAddress((void**)&vT_buf,   g_vT);
        cudaGetSymbolAddress((void**)&attn_buf, g_attn);
        cudaGetSymbolAddress((void**)&w_inT,    g_w_inT);
        cudaGetSymbolAddress((void**)&w_outT,   g_w_outT);
        cudaFuncSetAttribute(mha_mma_kernel,
                             cudaFuncAttributeMaxDynamicSharedMemorySize,
                             ATTN_SMEM_BYTES);
        cudaFuncSetAttribute(gemm_mma,
                             cudaFuncAttributeMaxDynamicSharedMemorySize,
                             GEMM_SMEM_BYTES);
        init = true;
    }

    // 0) Pre-round x; transpose+round weights to K-major tf32 bits.
    round_tf32_kernel<<<NTOK * EMB / 1024, 256>>>(x, x_buf);
    transpose_round_kernel<<<dim3(3 * EMB / 32, EMB / 32), dim3(32, 8)>>>(w_in,  w_inT,  EMB, 3 * EMB);
    transpose_round_kernel<<<dim3(EMB / 32,     EMB / 32), dim3(32, 8)>>>(w_out, w_outT, EMB, EMB);

    // 1) QKV projection (tf32 mma, 3-stage) — output rounded to tf32 bits.
    gemm_mma<<<dim3(3 * EMB / 128, NTOK / 128), 256, GEMM_SMEM_BYTES>>>(
        x_buf, w_inT, b_in, qkv_buf, NTOK, 3 * EMB, EMB, 1);

    // 1b) Transpose V into vT for cp.async-friendly attention loads.
    transpose_v_kernel<<<dim3(SEQ / 32, BATCH * NH * 2), dim3(32, 8)>>>(qkv_buf, vT_buf);

    // 2) Attention per (batch, head), 128-query tiles (tf32 mma flash, 4 warps)
    mha_mma_kernel<<<dim3(SEQ / 128, BATCH * NH), 128, ATTN_SMEM_BYTES>>>(
        qkv_buf, vT_buf, attn_buf);

    // 3) Output projection (tf32 mma, 3-stage) — final output, not rounded.
    gemm_mma<<<dim3(EMB / 128, NTOK / 128), 256, GEMM_SMEM_BYTES>>>(
        attn_buf, w_outT, b_out, out, NTOK, EMB, EMB, 0);
}